// round 1
// baseline (speedup 1.0000x reference)
#include <cuda_runtime.h>
#include <math.h>

// Problem constants
#define NTH   512
#define PAD   65            // smem row pad (65 mod 32 == 1 -> conflict-free broadcast/tr writes)
#define NV    16
#define ND    64
#define NH    256
#define NC    128
#define NTOK  8192          // B*T
#define TT    64            // tokens per block

// Scratch (device globals: allocation-free rule)
__device__ float g_ctxp[32 * NH];              // context projection (B,H)
__device__ float g_varout[NTOK * NV * NH];     // weighted per-variable outputs (134MB)

__device__ __forceinline__ float elu_f(float x)  { return x > 0.f ? x : (__expf(x) - 1.f); }
__device__ __forceinline__ float sigm_f(float x) { return 1.f / (1.f + __expf(-x)); }

#define FMA_ROW(ACC, XS) do { \
    ACC[0] += (XS) * w0.x; ACC[1] += (XS) * w0.y; ACC[2] += (XS) * w0.z; ACC[3] += (XS) * w0.w; \
    ACC[4] += (XS) * w1.x; ACC[5] += (XS) * w1.y; ACC[6] += (XS) * w1.z; ACC[7] += (XS) * w1.w; } while (0)

// ---------------------------------------------------------------------------
// Kernel 0: ctxp[b][h] = sum_c context[b][c] * wg_ctx_w[c][h]
// ---------------------------------------------------------------------------
__global__ void ctx_kernel(const float* __restrict__ ctx, const float* __restrict__ wctx)
{
    int b = blockIdx.x;
    int h = threadIdx.x;
    float acc = 0.f;
    for (int c = 0; c < NC; ++c)
        acc += ctx[b * NC + c] * wctx[c * NH + h];
    g_ctxp[b * NH + h] = acc;
}

// ---------------------------------------------------------------------------
// Kernel 1: weight GRN -> softmax weights (N,16), written to outw
// One block = 64 tokens, 512 threads. Thread tile: 4 tokens x 8 cols.
// ---------------------------------------------------------------------------
__global__ __launch_bounds__(NTH, 1)
void wg_kernel(const float* __restrict__ x,
               const float* __restrict__ fc1w, const float* __restrict__ fc1b,
               const float* __restrict__ fc2w, const float* __restrict__ fc2b,
               const float* __restrict__ gluw, const float* __restrict__ glub,
               const float* __restrict__ skw,  const float* __restrict__ skb,
               const float* __restrict__ lng,  const float* __restrict__ lnb,
               float* __restrict__ outw)
{
    extern __shared__ float sm[];
    float* sx  = sm;                       // [128][PAD]  k-tile of flat, [k][t]
    float* ash = sx  + 128 * PAD;          // [256][PAD]  h1, [c][t]
    float* bsh = ash + 256 * PAD;          // [256][PAD]  h2, [c][t]
    float* rsh = bsh + 256 * PAD;          // [64][16]    residual
    float* gsh = rsh + 64 * 16;            // [64][32]    glu pre-act

    const int tid  = threadIdx.x;
    const int warp = tid >> 5, lane = tid & 31;
    const int t0 = warp * 4;               // 16 warps * 4 tokens
    const int c0 = lane * 8;               // 32 lanes * 8 cols
    const int n0 = blockIdx.x * TT;
    const int tR = tid >> 3, jR = tid & 7; // residual mapping: token tR, cols jR & jR+8

    float acc[4][8];
#pragma unroll
    for (int i = 0; i < 4; ++i)
#pragma unroll
        for (int j = 0; j < 8; ++j) acc[i][j] = 0.f;
    float r0 = 0.f, r1 = 0.f;

    // ---- stage 1: h1 = flat @ fc1 (K=1024, 8 k-tiles) + residual = flat @ skip ----
    for (int kt = 0; kt < 8; ++kt) {
        for (int i = tid; i < TT * 128; i += NTH) {
            int t = i >> 7, k = i & 127;
            sx[k * PAD + t] = x[(size_t)(n0 + t) * 1024 + kt * 128 + k];
        }
        __syncthreads();
        const float* W = fc1w + (size_t)(kt * 128) * NH + c0;
#pragma unroll 2
        for (int k = 0; k < 128; ++k) {
            float4 w0 = *(const float4*)(W + (size_t)k * NH);
            float4 w1 = *(const float4*)(W + (size_t)k * NH + 4);
            float xs0 = sx[k * PAD + t0 + 0];
            float xs1 = sx[k * PAD + t0 + 1];
            float xs2 = sx[k * PAD + t0 + 2];
            float xs3 = sx[k * PAD + t0 + 3];
            FMA_ROW(acc[0], xs0); FMA_ROW(acc[1], xs1);
            FMA_ROW(acc[2], xs2); FMA_ROW(acc[3], xs3);
        }
        const float* Ws = skw + (size_t)(kt * 128) * NV;
#pragma unroll 4
        for (int k = 0; k < 128; ++k) {
            float xv = sx[k * PAD + tR];
            r0 += xv * Ws[k * NV + jR];
            r1 += xv * Ws[k * NV + jR + 8];
        }
        __syncthreads();
    }

    // bias + context + elu -> ash[c][t]
    {
        const int b = n0 >> 8;  // 64 | 256 so tile lies in one batch
#pragma unroll
        for (int j = 0; j < 8; ++j) {
            float bb = fc1b[c0 + j] + g_ctxp[b * NH + c0 + j];
#pragma unroll
            for (int i = 0; i < 4; ++i)
                ash[(c0 + j) * PAD + t0 + i] = elu_f(acc[i][j] + bb);
        }
        rsh[tR * 16 + jR]     = r0 + skb[jR];
        rsh[tR * 16 + jR + 8] = r1 + skb[jR + 8];
    }
    __syncthreads();

    // ---- stage 2: h2 = h1 @ fc2 + b2 -> bsh ----
#pragma unroll
    for (int i = 0; i < 4; ++i)
#pragma unroll
        for (int j = 0; j < 8; ++j) acc[i][j] = 0.f;
    {
        const float* W2 = fc2w + c0;
#pragma unroll 2
        for (int k = 0; k < NH; ++k) {
            float4 w0 = *(const float4*)(W2 + (size_t)k * NH);
            float4 w1 = *(const float4*)(W2 + (size_t)k * NH + 4);
            float xs0 = ash[k * PAD + t0 + 0];
            float xs1 = ash[k * PAD + t0 + 1];
            float xs2 = ash[k * PAD + t0 + 2];
            float xs3 = ash[k * PAD + t0 + 3];
            FMA_ROW(acc[0], xs0); FMA_ROW(acc[1], xs1);
            FMA_ROW(acc[2], xs2); FMA_ROW(acc[3], xs3);
        }
#pragma unroll
        for (int j = 0; j < 8; ++j) {
            float bb = fc2b[c0 + j];
#pragma unroll
            for (int i = 0; i < 4; ++i)
                bsh[(c0 + j) * PAD + t0 + i] = acc[i][j] + bb;
        }
    }
    __syncthreads();

    // ---- stage 3: g = h2 @ glu_w + glu_b  (K=256 -> 32 cols) ----
    {
        float a3[4] = {0.f, 0.f, 0.f, 0.f};
#pragma unroll 4
        for (int k = 0; k < NH; ++k) {
            float w = gluw[k * 32 + lane];
            a3[0] += bsh[k * PAD + t0 + 0] * w;
            a3[1] += bsh[k * PAD + t0 + 1] * w;
            a3[2] += bsh[k * PAD + t0 + 2] * w;
            a3[3] += bsh[k * PAD + t0 + 3] * w;
        }
        float gb = glub[lane];
#pragma unroll
        for (int i = 0; i < 4; ++i)
            gsh[(t0 + i) * 32 + lane] = a3[i] + gb;
    }
    __syncthreads();

    // ---- stage 4: GLU + residual + LN(16) + softmax(16) ----
    if (tid < TT) {
        int t = tid;
        float h[NV];
        float mu = 0.f;
#pragma unroll
        for (int v = 0; v < NV; ++v) {
            float a  = gsh[t * 32 + v];
            float bb = gsh[t * 32 + 16 + v];
            h[v] = a * sigm_f(bb) + rsh[t * 16 + v];
            mu += h[v];
        }
        mu *= (1.f / 16.f);
        float var = 0.f;
#pragma unroll
        for (int v = 0; v < NV; ++v) { float d = h[v] - mu; var += d * d; }
        var *= (1.f / 16.f);
        float rstd = rsqrtf(var + 1e-5f);
        float y[NV], m = -1e30f;
#pragma unroll
        for (int v = 0; v < NV; ++v) {
            y[v] = (h[v] - mu) * rstd * lng[v] + lnb[v];
            m = fmaxf(m, y[v]);
        }
        float s = 0.f;
#pragma unroll
        for (int v = 0; v < NV; ++v) { y[v] = __expf(y[v] - m); s += y[v]; }
        float inv = 1.f / s;
#pragma unroll
        for (int v = 0; v < NV; ++v)
            outw[(n0 + t) * NV + v] = y[v] * inv;
    }
}

// ---------------------------------------------------------------------------
// Kernel 2: per-variable GRN, one block = (64 tokens, one variable).
// Writes weight-scaled LN output into g_varout (no atomics).
// ---------------------------------------------------------------------------
__global__ __launch_bounds__(NTH, 1)
void vg_kernel(const float* __restrict__ x,
               const float* __restrict__ fc1w, const float* __restrict__ fc1b,
               const float* __restrict__ fc2w, const float* __restrict__ fc2b,
               const float* __restrict__ gluw, const float* __restrict__ glub,
               const float* __restrict__ skw,  const float* __restrict__ skb,
               const float* __restrict__ lng,  const float* __restrict__ lnb,
               const float* __restrict__ weights)
{
    extern __shared__ float sm[];
    float* sx  = sm;                       // [64][PAD]   x tile, [d][t]
    float* ash = sx  + 64 * PAD;           // [256][PAD]  h1 / then hv, [c][t]
    float* bsh = ash + 256 * PAD;          // [256][PAD]  h2, [c][t]
    float* rsh = bsh + 256 * PAD;          // [256][PAD]  residual, [c][t]

    const int v  = blockIdx.y;
    const int n0 = blockIdx.x * TT;
    const int tid  = threadIdx.x;
    const int warp = tid >> 5, lane = tid & 31;
    const int t0 = warp * 4;
    const int c0 = lane * 8;

    for (int i = tid; i < TT * ND; i += NTH) {
        int t = i >> 6, d = i & 63;
        sx[d * PAD + t] = x[((size_t)(n0 + t) * NV + v) * ND + d];
    }
    __syncthreads();

    float acc[4][8];

    // ---- stage 1a: h1 = elu(x @ fc1 + b1) -> ash ----
    {
#pragma unroll
        for (int i = 0; i < 4; ++i)
#pragma unroll
            for (int j = 0; j < 8; ++j) acc[i][j] = 0.f;
        const float* W1 = fc1w + (size_t)v * ND * NH + c0;
#pragma unroll 2
        for (int k = 0; k < ND; ++k) {
            float4 w0 = *(const float4*)(W1 + (size_t)k * NH);
            float4 w1 = *(const float4*)(W1 + (size_t)k * NH + 4);
            float xs0 = sx[k * PAD + t0 + 0];
            float xs1 = sx[k * PAD + t0 + 1];
            float xs2 = sx[k * PAD + t0 + 2];
            float xs3 = sx[k * PAD + t0 + 3];
            FMA_ROW(acc[0], xs0); FMA_ROW(acc[1], xs1);
            FMA_ROW(acc[2], xs2); FMA_ROW(acc[3], xs3);
        }
#pragma unroll
        for (int j = 0; j < 8; ++j) {
            float bb = fc1b[v * NH + c0 + j];
#pragma unroll
            for (int i = 0; i < 4; ++i)
                ash[(c0 + j) * PAD + t0 + i] = elu_f(acc[i][j] + bb);
        }
    }

    // ---- stage 1b: residual = x @ skip + bs -> rsh ----
    {
#pragma unroll
        for (int i = 0; i < 4; ++i)
#pragma unroll
            for (int j = 0; j < 8; ++j) acc[i][j] = 0.f;
        const float* Ws = skw + (size_t)v * ND * NH + c0;
#pragma unroll 2
        for (int k = 0; k < ND; ++k) {
            float4 w0 = *(const float4*)(Ws + (size_t)k * NH);
            float4 w1 = *(const float4*)(Ws + (size_t)k * NH + 4);
            float xs0 = sx[k * PAD + t0 + 0];
            float xs1 = sx[k * PAD + t0 + 1];
            float xs2 = sx[k * PAD + t0 + 2];
            float xs3 = sx[k * PAD + t0 + 3];
            FMA_ROW(acc[0], xs0); FMA_ROW(acc[1], xs1);
            FMA_ROW(acc[2], xs2); FMA_ROW(acc[3], xs3);
        }
#pragma unroll
        for (int j = 0; j < 8; ++j) {
            float bb = skb[v * NH + c0 + j];
#pragma unroll
            for (int i = 0; i < 4; ++i)
                rsh[(c0 + j) * PAD + t0 + i] = acc[i][j] + bb;
        }
    }
    __syncthreads();

    // ---- stage 2: h2 = h1 @ fc2 + b2 -> bsh ----
    {
#pragma unroll
        for (int i = 0; i < 4; ++i)
#pragma unroll
            for (int j = 0; j < 8; ++j) acc[i][j] = 0.f;
        const float* W2 = fc2w + (size_t)v * NH * NH + c0;
#pragma unroll 2
        for (int k = 0; k < NH; ++k) {
            float4 w0 = *(const float4*)(W2 + (size_t)k * NH);
            float4 w1 = *(const float4*)(W2 + (size_t)k * NH + 4);
            float xs0 = ash[k * PAD + t0 + 0];
            float xs1 = ash[k * PAD + t0 + 1];
            float xs2 = ash[k * PAD + t0 + 2];
            float xs3 = ash[k * PAD + t0 + 3];
            FMA_ROW(acc[0], xs0); FMA_ROW(acc[1], xs1);
            FMA_ROW(acc[2], xs2); FMA_ROW(acc[3], xs3);
        }
#pragma unroll
        for (int j = 0; j < 8; ++j) {
            float bb = fc2b[v * NH + c0 + j];
#pragma unroll
            for (int i = 0; i < 4; ++i)
                bsh[(c0 + j) * PAD + t0 + i] = acc[i][j] + bb;
        }
    }
    __syncthreads();   // bsh ready; ash now dead (safe to overwrite after this)

    // ---- stage 3: GLU (a,b halves of h2 @ glu_w) + residual -> hv -> ash ----
    {
        const float* Wg = gluw + (size_t)v * NH * 512;
#pragma unroll
        for (int half = 0; half < 2; ++half) {
            const int cb = c0 + half * 4;
            float aa[4][4], ab[4][4];
#pragma unroll
            for (int i = 0; i < 4; ++i)
#pragma unroll
                for (int j = 0; j < 4; ++j) { aa[i][j] = 0.f; ab[i][j] = 0.f; }
#pragma unroll 2
            for (int k = 0; k < NH; ++k) {
                float4 wa = *(const float4*)(Wg + (size_t)k * 512 + cb);
                float4 wb = *(const float4*)(Wg + (size_t)k * 512 + 256 + cb);
                float xs0 = bsh[k * PAD + t0 + 0];
                float xs1 = bsh[k * PAD + t0 + 1];
                float xs2 = bsh[k * PAD + t0 + 2];
                float xs3 = bsh[k * PAD + t0 + 3];
                aa[0][0] += xs0 * wa.x; aa[0][1] += xs0 * wa.y; aa[0][2] += xs0 * wa.z; aa[0][3] += xs0 * wa.w;
                aa[1][0] += xs1 * wa.x; aa[1][1] += xs1 * wa.y; aa[1][2] += xs1 * wa.z; aa[1][3] += xs1 * wa.w;
                aa[2][0] += xs2 * wa.x; aa[2][1] += xs2 * wa.y; aa[2][2] += xs2 * wa.z; aa[2][3] += xs2 * wa.w;
                aa[3][0] += xs3 * wa.x; aa[3][1] += xs3 * wa.y; aa[3][2] += xs3 * wa.z; aa[3][3] += xs3 * wa.w;
                ab[0][0] += xs0 * wb.x; ab[0][1] += xs0 * wb.y; ab[0][2] += xs0 * wb.z; ab[0][3] += xs0 * wb.w;
                ab[1][0] += xs1 * wb.x; ab[1][1] += xs1 * wb.y; ab[1][2] += xs1 * wb.z; ab[1][3] += xs1 * wb.w;
                ab[2][0] += xs2 * wb.x; ab[2][1] += xs2 * wb.y; ab[2][2] += xs2 * wb.z; ab[2][3] += xs2 * wb.w;
                ab[3][0] += xs3 * wb.x; ab[3][1] += xs3 * wb.y; ab[3][2] += xs3 * wb.z; ab[3][3] += xs3 * wb.w;
            }
#pragma unroll
            for (int j = 0; j < 4; ++j) {
                float ba = glub[v * 512 + cb + j];
                float bb = glub[v * 512 + 256 + cb + j];
#pragma unroll
                for (int i = 0; i < 4; ++i) {
                    float a  = aa[i][j] + ba;
                    float g  = ab[i][j] + bb;
                    float hv = a * sigm_f(g) + rsh[(cb + j) * PAD + t0 + i];
                    ash[(cb + j) * PAD + t0 + i] = hv;   // own slots; ash dead since stage2
                }
            }
        }
    }
    __syncthreads();

    // ---- stage 4: LayerNorm(256) per token, scale by weight, write varout ----
    {
        int t = tid >> 3;      // 0..63
        int j = tid & 7;
        float s = 0.f, s2 = 0.f;
        for (int c = j; c < NH; c += 8) {
            float u = ash[c * PAD + t];
            s += u; s2 += u * u;
        }
#pragma unroll
        for (int off = 4; off > 0; off >>= 1) {
            s  += __shfl_xor_sync(0xffffffffu, s,  off, 8);
            s2 += __shfl_xor_sync(0xffffffffu, s2, off, 8);
        }
        float mu   = s * (1.f / 256.f);
        float var  = s2 * (1.f / 256.f) - mu * mu;
        float rstd = rsqrtf(var + 1e-5f);
        float w = weights[(n0 + t) * NV + v];
        float* dst = g_varout + ((size_t)(n0 + t) * NV + v) * NH;
        const float* gv = lng + v * NH;
        const float* bv = lnb + v * NH;
        for (int c = j; c < NH; c += 8) {
            float u = ash[c * PAD + t];
            float o = (u - mu) * rstd * gv[c] + bv[c];
            dst[c] = o * w;
        }
    }
}

// ---------------------------------------------------------------------------
// Kernel 3: selected[n][c] = sum_v varout[n][v][c]
// ---------------------------------------------------------------------------
__global__ void combine_kernel(float* __restrict__ out_sel)
{
    int n = blockIdx.x;
    int c = threadIdx.x;
    const float* p = g_varout + (size_t)n * NV * NH + c;
    float s = 0.f;
#pragma unroll
    for (int v = 0; v < NV; ++v) s += p[v * NH];
    out_sel[(size_t)n * NH + c] = s;
}

// ---------------------------------------------------------------------------
extern "C" void kernel_launch(void* const* d_in, const int* in_sizes, int n_in,
                              void* d_out, int out_size)
{
    const float* x        = (const float*)d_in[0];
    const float* context  = (const float*)d_in[1];
    const float* vg_fc1_w = (const float*)d_in[2];
    const float* vg_fc1_b = (const float*)d_in[3];
    const float* vg_fc2_w = (const float*)d_in[4];
    const float* vg_fc2_b = (const float*)d_in[5];
    const float* vg_glu_w = (const float*)d_in[6];
    const float* vg_glu_b = (const float*)d_in[7];
    const float* vg_skip_w= (const float*)d_in[8];
    const float* vg_skip_b= (const float*)d_in[9];
    const float* vg_ln_g  = (const float*)d_in[10];
    const float* vg_ln_b  = (const float*)d_in[11];
    const float* wg_fc1_w = (const float*)d_in[12];
    const float* wg_fc1_b = (const float*)d_in[13];
    const float* wg_ctx_w = (const float*)d_in[14];
    const float* wg_fc2_w = (const float*)d_in[15];
    const float* wg_fc2_b = (const float*)d_in[16];
    const float* wg_glu_w = (const float*)d_in[17];
    const float* wg_glu_b = (const float*)d_in[18];
    const float* wg_skip_w= (const float*)d_in[19];
    const float* wg_skip_b= (const float*)d_in[20];
    const float* wg_ln_g  = (const float*)d_in[21];
    const float* wg_ln_b  = (const float*)d_in[22];

    float* out      = (float*)d_out;
    float* out_sel  = out;                     // (B,T,H) = 8192*256
    float* out_wts  = out + (size_t)NTOK * NH; // (B,T,V) = 8192*16

    const int WG_SMEM = (128 * PAD + 2 * 256 * PAD + 64 * 16 + 64 * 32) * 4; // 178688
    const int VG_SMEM = (64 * PAD + 3 * 256 * PAD) * 4;                      // 216320
    cudaFuncSetAttribute(wg_kernel, cudaFuncAttributeMaxDynamicSharedMemorySize, WG_SMEM);
    cudaFuncSetAttribute(vg_kernel, cudaFuncAttributeMaxDynamicSharedMemorySize, VG_SMEM);

    ctx_kernel<<<32, NH>>>(context, wg_ctx_w);

    wg_kernel<<<NTOK / TT, NTH, WG_SMEM>>>(
        x, wg_fc1_w, wg_fc1_b, wg_fc2_w, wg_fc2_b,
        wg_glu_w, wg_glu_b, wg_skip_w, wg_skip_b, wg_ln_g, wg_ln_b, out_wts);

    vg_kernel<<<dim3(NTOK / TT, NV), NTH, VG_SMEM>>>(
        x, vg_fc1_w, vg_fc1_b, vg_fc2_w, vg_fc2_b,
        vg_glu_w, vg_glu_b, vg_skip_w, vg_skip_b, vg_ln_g, vg_ln_b, out_wts);

    combine_kernel<<<NTOK, NH>>>(out_sel);
}

// round 2
// speedup vs baseline: 1.0165x; 1.0165x over previous
#include <cuda_runtime.h>
#include <math.h>

// Problem constants
#define NTH   512
#define PAD   65
#define NV    16
#define ND    64
#define NH    256
#define NC    128
#define NTOK  8192
#define TT    64

typedef unsigned long long u64;

// Scratch (device globals: allocation-free rule)
__device__ float g_ctxp[32 * NH];
__device__ float g_varout[NTOK * NV * NH];

__device__ __forceinline__ float elu_f(float x)  { return x > 0.f ? x : (__expf(x) - 1.f); }
__device__ __forceinline__ float sigm_f(float x) { return 1.f / (1.f + __expf(-x)); }

// ---- packed fp32x2 helpers (Blackwell FFMA2 path; ptxas never auto-fuses) ----
__device__ __forceinline__ u64 pk2(float a, float b) {
    u64 r; asm("mov.b64 %0, {%1, %2};" : "=l"(r) : "f"(a), "f"(b)); return r;
}
__device__ __forceinline__ void fm2(u64& d, u64 a, u64 b) {
    asm("fma.rn.f32x2 %0, %1, %2, %0;" : "+l"(d) : "l"(a), "l"(b));
}
__device__ __forceinline__ float2 up2(u64 v) {
    float2 f; asm("mov.b64 {%0, %1}, %2;" : "=f"(f.x), "=f"(f.y) : "l"(v)); return f;
}

// One k-step of the 4-token x 8-col (4 col-pair) register tile.
// Requires in scope: ulonglong2 wA, wB; floats xs0..xs3.
#define GSTEP(ACC) do { \
    u64 _xp; \
    _xp = pk2(xs0, xs0); fm2(ACC[0][0], wA.x, _xp); fm2(ACC[0][1], wA.y, _xp); fm2(ACC[0][2], wB.x, _xp); fm2(ACC[0][3], wB.y, _xp); \
    _xp = pk2(xs1, xs1); fm2(ACC[1][0], wA.x, _xp); fm2(ACC[1][1], wA.y, _xp); fm2(ACC[1][2], wB.x, _xp); fm2(ACC[1][3], wB.y, _xp); \
    _xp = pk2(xs2, xs2); fm2(ACC[2][0], wA.x, _xp); fm2(ACC[2][1], wA.y, _xp); fm2(ACC[2][2], wB.x, _xp); fm2(ACC[2][3], wB.y, _xp); \
    _xp = pk2(xs3, xs3); fm2(ACC[3][0], wA.x, _xp); fm2(ACC[3][1], wA.y, _xp); fm2(ACC[3][2], wB.x, _xp); fm2(ACC[3][3], wB.y, _xp); \
} while (0)

#define ZERO44(ACC) do { \
    _Pragma("unroll") for (int _i = 0; _i < 4; ++_i) \
    _Pragma("unroll") for (int _j = 0; _j < 4; ++_j) ACC[_i][_j] = 0ull; \
} while (0)

// ---------------------------------------------------------------------------
// Kernel 0: ctxp[b][h] = sum_c context[b][c] * wg_ctx_w[c][h]
// ---------------------------------------------------------------------------
__global__ void ctx_kernel(const float* __restrict__ ctx, const float* __restrict__ wctx)
{
    int b = blockIdx.x;
    int h = threadIdx.x;
    float acc = 0.f;
    for (int c = 0; c < NC; ++c)
        acc += ctx[b * NC + c] * wctx[c * NH + h];
    g_ctxp[b * NH + h] = acc;
}

// ---------------------------------------------------------------------------
// Kernel 1: weight GRN -> softmax weights (N,16)
// ---------------------------------------------------------------------------
__global__ __launch_bounds__(NTH, 1)
void wg_kernel(const float* __restrict__ x,
               const float* __restrict__ fc1w, const float* __restrict__ fc1b,
               const float* __restrict__ fc2w, const float* __restrict__ fc2b,
               const float* __restrict__ gluw, const float* __restrict__ glub,
               const float* __restrict__ skw,  const float* __restrict__ skb,
               const float* __restrict__ lng,  const float* __restrict__ lnb,
               float* __restrict__ outw)
{
    extern __shared__ float sm[];
    float* sx  = sm;                       // [128][PAD]
    float* ash = sx  + 128 * PAD;          // [256][PAD]
    float* bsh = ash + 256 * PAD;          // [256][PAD]
    float* rsh = bsh + 256 * PAD;          // [64][16]
    float* gsh = rsh + 64 * 16;            // [64][32]

    const int tid  = threadIdx.x;
    const int warp = tid >> 5, lane = tid & 31;
    const int t0 = warp * 4;
    const int c0 = lane * 8;
    const int n0 = blockIdx.x * TT;
    const int tR = tid >> 3, jR = tid & 7;

    u64 acc[4][4];
    ZERO44(acc);
    float r0 = 0.f, r1 = 0.f;

    // ---- stage 1: h1 = flat @ fc1 (K=1024) + residual = flat @ skip ----
    for (int kt = 0; kt < 8; ++kt) {
        for (int i = tid; i < TT * 128; i += NTH) {
            int t = i >> 7, k = i & 127;
            sx[k * PAD + t] = x[(size_t)(n0 + t) * 1024 + kt * 128 + k];
        }
        __syncthreads();
        const float* W = fc1w + (size_t)(kt * 128) * NH + c0;
#pragma unroll 2
        for (int k = 0; k < 128; ++k) {
            ulonglong2 wA = *(const ulonglong2*)(W + (size_t)k * NH);
            ulonglong2 wB = *(const ulonglong2*)(W + (size_t)k * NH + 4);
            float xs0 = sx[k * PAD + t0 + 0];
            float xs1 = sx[k * PAD + t0 + 1];
            float xs2 = sx[k * PAD + t0 + 2];
            float xs3 = sx[k * PAD + t0 + 3];
            GSTEP(acc);
        }
        const float* Ws = skw + (size_t)(kt * 128) * NV;
#pragma unroll 4
        for (int k = 0; k < 128; ++k) {
            float xv = sx[k * PAD + tR];
            r0 += xv * Ws[k * NV + jR];
            r1 += xv * Ws[k * NV + jR + 8];
        }
        __syncthreads();
    }

    // bias + context + elu -> ash[c][t]
    {
        const int b = n0 >> 8;
#pragma unroll
        for (int j = 0; j < 4; ++j) {
            int ca = c0 + 2 * j, cb = ca + 1;
            float ba = fc1b[ca] + g_ctxp[b * NH + ca];
            float bb = fc1b[cb] + g_ctxp[b * NH + cb];
#pragma unroll
            for (int i = 0; i < 4; ++i) {
                float2 p = up2(acc[i][j]);
                ash[ca * PAD + t0 + i] = elu_f(p.x + ba);
                ash[cb * PAD + t0 + i] = elu_f(p.y + bb);
            }
        }
        rsh[tR * 16 + jR]     = r0 + skb[jR];
        rsh[tR * 16 + jR + 8] = r1 + skb[jR + 8];
    }
    __syncthreads();

    // ---- stage 2: h2 = h1 @ fc2 + b2 -> bsh ----
    ZERO44(acc);
    {
        const float* W2 = fc2w + c0;
#pragma unroll 2
        for (int k = 0; k < NH; ++k) {
            ulonglong2 wA = *(const ulonglong2*)(W2 + (size_t)k * NH);
            ulonglong2 wB = *(const ulonglong2*)(W2 + (size_t)k * NH + 4);
            float xs0 = ash[k * PAD + t0 + 0];
            float xs1 = ash[k * PAD + t0 + 1];
            float xs2 = ash[k * PAD + t0 + 2];
            float xs3 = ash[k * PAD + t0 + 3];
            GSTEP(acc);
        }
#pragma unroll
        for (int j = 0; j < 4; ++j) {
            int ca = c0 + 2 * j, cb = ca + 1;
            float ba = fc2b[ca], bb = fc2b[cb];
#pragma unroll
            for (int i = 0; i < 4; ++i) {
                float2 p = up2(acc[i][j]);
                bsh[ca * PAD + t0 + i] = p.x + ba;
                bsh[cb * PAD + t0 + i] = p.y + bb;
            }
        }
    }
    __syncthreads();

    // ---- stage 3: g = h2 @ glu_w + glu_b (K=256, 32 cols) ----
    {
        float a3[4] = {0.f, 0.f, 0.f, 0.f};
#pragma unroll 4
        for (int k = 0; k < NH; ++k) {
            float w = gluw[k * 32 + lane];
            a3[0] += bsh[k * PAD + t0 + 0] * w;
            a3[1] += bsh[k * PAD + t0 + 1] * w;
            a3[2] += bsh[k * PAD + t0 + 2] * w;
            a3[3] += bsh[k * PAD + t0 + 3] * w;
        }
        float gb = glub[lane];
#pragma unroll
        for (int i = 0; i < 4; ++i)
            gsh[(t0 + i) * 32 + lane] = a3[i] + gb;
    }
    __syncthreads();

    // ---- stage 4: GLU + residual + LN(16) + softmax(16) ----
    if (tid < TT) {
        int t = tid;
        float h[NV];
        float mu = 0.f;
#pragma unroll
        for (int v = 0; v < NV; ++v) {
            float a  = gsh[t * 32 + v];
            float bb = gsh[t * 32 + 16 + v];
            h[v] = a * sigm_f(bb) + rsh[t * 16 + v];
            mu += h[v];
        }
        mu *= (1.f / 16.f);
        float var = 0.f;
#pragma unroll
        for (int v = 0; v < NV; ++v) { float d = h[v] - mu; var += d * d; }
        var *= (1.f / 16.f);
        float rstd = rsqrtf(var + 1e-5f);
        float y[NV], m = -1e30f;
#pragma unroll
        for (int v = 0; v < NV; ++v) {
            y[v] = (h[v] - mu) * rstd * lng[v] + lnb[v];
            m = fmaxf(m, y[v]);
        }
        float s = 0.f;
#pragma unroll
        for (int v = 0; v < NV; ++v) { y[v] = __expf(y[v] - m); s += y[v]; }
        float inv = 1.f / s;
#pragma unroll
        for (int v = 0; v < NV; ++v)
            outw[(n0 + t) * NV + v] = y[v] * inv;
    }
}

// ---------------------------------------------------------------------------
// Kernel 2: per-variable GRN, one block = (64 tokens, one variable)
// ---------------------------------------------------------------------------
__global__ __launch_bounds__(NTH, 1)
void vg_kernel(const float* __restrict__ x,
               const float* __restrict__ fc1w, const float* __restrict__ fc1b,
               const float* __restrict__ fc2w, const float* __restrict__ fc2b,
               const float* __restrict__ gluw, const float* __restrict__ glub,
               const float* __restrict__ skw,  const float* __restrict__ skb,
               const float* __restrict__ lng,  const float* __restrict__ lnb,
               const float* __restrict__ weights)
{
    extern __shared__ float sm[];
    float* sx  = sm;                       // [64][PAD]
    float* ash = sx  + 64 * PAD;           // [256][PAD]
    float* bsh = ash + 256 * PAD;          // [256][PAD]
    float* rsh = bsh + 256 * PAD;          // [256][PAD]

    const int v  = blockIdx.y;
    const int n0 = blockIdx.x * TT;
    const int tid  = threadIdx.x;
    const int warp = tid >> 5, lane = tid & 31;
    const int t0 = warp * 4;
    const int c0 = lane * 8;

    for (int i = tid; i < TT * ND; i += NTH) {
        int t = i >> 6, d = i & 63;
        sx[d * PAD + t] = x[((size_t)(n0 + t) * NV + v) * ND + d];
    }
    __syncthreads();

    u64 acc[4][4];

    // ---- stage 1a: h1 = elu(x @ fc1 + b1) -> ash ----
    {
        ZERO44(acc);
        const float* W1 = fc1w + (size_t)v * ND * NH + c0;
#pragma unroll 2
        for (int k = 0; k < ND; ++k) {
            ulonglong2 wA = *(const ulonglong2*)(W1 + (size_t)k * NH);
            ulonglong2 wB = *(const ulonglong2*)(W1 + (size_t)k * NH + 4);
            float xs0 = sx[k * PAD + t0 + 0];
            float xs1 = sx[k * PAD + t0 + 1];
            float xs2 = sx[k * PAD + t0 + 2];
            float xs3 = sx[k * PAD + t0 + 3];
            GSTEP(acc);
        }
#pragma unroll
        for (int j = 0; j < 4; ++j) {
            int ca = c0 + 2 * j, cb = ca + 1;
            float ba = fc1b[v * NH + ca], bb = fc1b[v * NH + cb];
#pragma unroll
            for (int i = 0; i < 4; ++i) {
                float2 p = up2(acc[i][j]);
                ash[ca * PAD + t0 + i] = elu_f(p.x + ba);
                ash[cb * PAD + t0 + i] = elu_f(p.y + bb);
            }
        }
    }

    // ---- stage 1b: residual = x @ skip + bs -> rsh ----
    {
        ZERO44(acc);
        const float* Ws = skw + (size_t)v * ND * NH + c0;
#pragma unroll 2
        for (int k = 0; k < ND; ++k) {
            ulonglong2 wA = *(const ulonglong2*)(Ws + (size_t)k * NH);
            ulonglong2 wB = *(const ulonglong2*)(Ws + (size_t)k * NH + 4);
            float xs0 = sx[k * PAD + t0 + 0];
            float xs1 = sx[k * PAD + t0 + 1];
            float xs2 = sx[k * PAD + t0 + 2];
            float xs3 = sx[k * PAD + t0 + 3];
            GSTEP(acc);
        }
#pragma unroll
        for (int j = 0; j < 4; ++j) {
            int ca = c0 + 2 * j, cb = ca + 1;
            float ba = skb[v * NH + ca], bb = skb[v * NH + cb];
#pragma unroll
            for (int i = 0; i < 4; ++i) {
                float2 p = up2(acc[i][j]);
                rsh[ca * PAD + t0 + i] = p.x + ba;
                rsh[cb * PAD + t0 + i] = p.y + bb;
            }
        }
    }
    __syncthreads();

    // ---- stage 2: h2 = h1 @ fc2 + b2 -> bsh ----
    {
        ZERO44(acc);
        const float* W2 = fc2w + (size_t)v * NH * NH + c0;
#pragma unroll 2
        for (int k = 0; k < NH; ++k) {
            ulonglong2 wA = *(const ulonglong2*)(W2 + (size_t)k * NH);
            ulonglong2 wB = *(const ulonglong2*)(W2 + (size_t)k * NH + 4);
            float xs0 = ash[k * PAD + t0 + 0];
            float xs1 = ash[k * PAD + t0 + 1];
            float xs2 = ash[k * PAD + t0 + 2];
            float xs3 = ash[k * PAD + t0 + 3];
            GSTEP(acc);
        }
#pragma unroll
        for (int j = 0; j < 4; ++j) {
            int ca = c0 + 2 * j, cb = ca + 1;
            float ba = fc2b[v * NH + ca], bb = fc2b[v * NH + cb];
#pragma unroll
            for (int i = 0; i < 4; ++i) {
                float2 p = up2(acc[i][j]);
                bsh[ca * PAD + t0 + i] = p.x + ba;
                bsh[cb * PAD + t0 + i] = p.y + bb;
            }
        }
    }
    __syncthreads();   // bsh ready; ash now dead

    // ---- stage 3: GLU halves + residual -> hv -> ash ----
    {
        const float* Wg = gluw + (size_t)v * NH * 512;
#pragma unroll
        for (int half = 0; half < 2; ++half) {
            const int cb4 = c0 + half * 4;
            u64 aa[4][2], ab[4][2];
#pragma unroll
            for (int i = 0; i < 4; ++i) {
                aa[i][0] = aa[i][1] = 0ull;
                ab[i][0] = ab[i][1] = 0ull;
            }
#pragma unroll 2
            for (int k = 0; k < NH; ++k) {
                ulonglong2 wa = *(const ulonglong2*)(Wg + (size_t)k * 512 + cb4);
                ulonglong2 wb = *(const ulonglong2*)(Wg + (size_t)k * 512 + 256 + cb4);
                float xs0 = bsh[k * PAD + t0 + 0];
                float xs1 = bsh[k * PAD + t0 + 1];
                float xs2 = bsh[k * PAD + t0 + 2];
                float xs3 = bsh[k * PAD + t0 + 3];
                u64 xp;
                xp = pk2(xs0, xs0); fm2(aa[0][0], wa.x, xp); fm2(aa[0][1], wa.y, xp); fm2(ab[0][0], wb.x, xp); fm2(ab[0][1], wb.y, xp);
                xp = pk2(xs1, xs1); fm2(aa[1][0], wa.x, xp); fm2(aa[1][1], wa.y, xp); fm2(ab[1][0], wb.x, xp); fm2(ab[1][1], wb.y, xp);
                xp = pk2(xs2, xs2); fm2(aa[2][0], wa.x, xp); fm2(aa[2][1], wa.y, xp); fm2(ab[2][0], wb.x, xp); fm2(ab[2][1], wb.y, xp);
                xp = pk2(xs3, xs3); fm2(aa[3][0], wa.x, xp); fm2(aa[3][1], wa.y, xp); fm2(ab[3][0], wb.x, xp); fm2(ab[3][1], wb.y, xp);
            }
#pragma unroll
            for (int j = 0; j < 2; ++j) {
                int ca = cb4 + 2 * j, cc = ca + 1;
                float ba0 = glub[v * 512 + ca],       ba1 = glub[v * 512 + cc];
                float bb0 = glub[v * 512 + 256 + ca], bb1 = glub[v * 512 + 256 + cc];
#pragma unroll
                for (int i = 0; i < 4; ++i) {
                    float2 pa = up2(aa[i][j]);
                    float2 pb = up2(ab[i][j]);
                    float hv0 = (pa.x + ba0) * sigm_f(pb.x + bb0) + rsh[ca * PAD + t0 + i];
                    float hv1 = (pa.y + ba1) * sigm_f(pb.y + bb1) + rsh[cc * PAD + t0 + i];
                    ash[ca * PAD + t0 + i] = hv0;
                    ash[cc * PAD + t0 + i] = hv1;
                }
            }
        }
    }
    __syncthreads();

    // ---- stage 4: LayerNorm(256), scale by weight, write varout ----
    {
        int t = tid >> 3;
        int j = tid & 7;
        float s = 0.f, s2 = 0.f;
        for (int c = j; c < NH; c += 8) {
            float u = ash[c * PAD + t];
            s += u; s2 += u * u;
        }
#pragma unroll
        for (int off = 4; off > 0; off >>= 1) {
            s  += __shfl_xor_sync(0xffffffffu, s,  off, 8);
            s2 += __shfl_xor_sync(0xffffffffu, s2, off, 8);
        }
        float mu   = s * (1.f / 256.f);
        float var  = s2 * (1.f / 256.f) - mu * mu;
        float rstd = rsqrtf(var + 1e-5f);
        float w = weights[(n0 + t) * NV + v];
        float* dst = g_varout + ((size_t)(n0 + t) * NV + v) * NH;
        const float* gv = lng + v * NH;
        const float* bv = lnb + v * NH;
        for (int c = j; c < NH; c += 8) {
            float u = ash[c * PAD + t];
            float o = (u - mu) * rstd * gv[c] + bv[c];
            dst[c] = o * w;
        }
    }
}

// ---------------------------------------------------------------------------
// Kernel 3: selected[n][c] = sum_v varout[n][v][c]
// ---------------------------------------------------------------------------
__global__ void combine_kernel(float* __restrict__ out_sel)
{
    int n = blockIdx.x;
    int c = threadIdx.x;
    const float* p = g_varout + (size_t)n * NV * NH + c;
    float s = 0.f;
#pragma unroll
    for (int v = 0; v < NV; ++v) s += p[v * NH];
    out_sel[(size_t)n * NH + c] = s;
}

// ---------------------------------------------------------------------------
extern "C" void kernel_launch(void* const* d_in, const int* in_sizes, int n_in,
                              void* d_out, int out_size)
{
    const float* x        = (const float*)d_in[0];
    const float* context  = (const float*)d_in[1];
    const float* vg_fc1_w = (const float*)d_in[2];
    const float* vg_fc1_b = (const float*)d_in[3];
    const float* vg_fc2_w = (const float*)d_in[4];
    const float* vg_fc2_b = (const float*)d_in[5];
    const float* vg_glu_w = (const float*)d_in[6];
    const float* vg_glu_b = (const float*)d_in[7];
    const float* vg_skip_w= (const float*)d_in[8];
    const float* vg_skip_b= (const float*)d_in[9];
    const float* vg_ln_g  = (const float*)d_in[10];
    const float* vg_ln_b  = (const float*)d_in[11];
    const float* wg_fc1_w = (const float*)d_in[12];
    const float* wg_fc1_b = (const float*)d_in[13];
    const float* wg_ctx_w = (const float*)d_in[14];
    const float* wg_fc2_w = (const float*)d_in[15];
    const float* wg_fc2_b = (const float*)d_in[16];
    const float* wg_glu_w = (const float*)d_in[17];
    const float* wg_glu_b = (const float*)d_in[18];
    const float* wg_skip_w= (const float*)d_in[19];
    const float* wg_skip_b= (const float*)d_in[20];
    const float* wg_ln_g  = (const float*)d_in[21];
    const float* wg_ln_b  = (const float*)d_in[22];

    float* out      = (float*)d_out;
    float* out_sel  = out;
    float* out_wts  = out + (size_t)NTOK * NH;

    const int WG_SMEM = (128 * PAD + 2 * 256 * PAD + 64 * 16 + 64 * 32) * 4;
    const int VG_SMEM = (64 * PAD + 3 * 256 * PAD) * 4;
    cudaFuncSetAttribute(wg_kernel, cudaFuncAttributeMaxDynamicSharedMemorySize, WG_SMEM);
    cudaFuncSetAttribute(vg_kernel, cudaFuncAttributeMaxDynamicSharedMemorySize, VG_SMEM);

    ctx_kernel<<<32, NH>>>(context, wg_ctx_w);

    wg_kernel<<<NTOK / TT, NTH, WG_SMEM>>>(
        x, wg_fc1_w, wg_fc1_b, wg_fc2_w, wg_fc2_b,
        wg_glu_w, wg_glu_b, wg_skip_w, wg_skip_b, wg_ln_g, wg_ln_b, out_wts);

    vg_kernel<<<dim3(NTOK / TT, NV), NTH, VG_SMEM>>>(
        x, vg_fc1_w, vg_fc1_b, vg_fc2_w, vg_fc2_b,
        vg_glu_w, vg_glu_b, vg_skip_w, vg_skip_b, vg_ln_g, vg_ln_b, out_wts);

    combine_kernel<<<NTOK, NH>>>(out_sel);
}